// round 2
// baseline (speedup 1.0000x reference)
#include <cuda_runtime.h>
#include <math.h>
#include <stdint.h>
#include <stddef.h>

#define BB   32
#define NN   196
#define TT   128
#define DIMG 768
#define DH   512
#define VV   10000

// ---------------- scratch (device globals; no allocation allowed) ----------
__device__ float g_keys[BB * NN * DH];     // 12.8 MB
__device__ float g_Wk[BB * NN * DH];       // 12.8 MB
__device__ float g_h[BB * DH];
__device__ float g_c[BB * DH];
__device__ float g_z[BB * 2 * DH];         // [x_t | ctx]
__device__ float g_H[BB * TT * DH];        // all h_new, for deferred logits GEMM
__device__ float g_pih[16 * BB * 2048];    // z @ W_ih^T partials (K=1024 -> 16 slots)
__device__ float g_phh[8 * BB * 2048];     // h @ W_hh^T partials (K=512 -> 8 slots)
__device__ float g_phwh[8 * BB * DH];      // h @ attn_Wh^T partials (K=512 -> 8 slots)

// ---------------- small device helpers -------------------------------------
__device__ __forceinline__ float tanh_fast(float x) {
    float y;
    asm("tanh.approx.f32 %0, %1;" : "=f"(y) : "f"(x));
    return y;
}
__device__ __forceinline__ float sigmoidf_acc(float x) {
    return 1.0f / (1.0f + expf(-x));
}
__device__ __forceinline__ float warp_sum(float v) {
#pragma unroll
    for (int o = 16; o > 0; o >>= 1) v += __shfl_xor_sync(0xffffffffu, v, o);
    return v;
}
__device__ __forceinline__ float warp_max(float v) {
#pragma unroll
    for (int o = 16; o > 0; o >>= 1) v = fmaxf(v, __shfl_xor_sync(0xffffffffu, v, o));
    return v;
}
// block reductions for blockDim.x == 512 (16 warps). red must hold 16 floats.
__device__ __forceinline__ float block_sum512(float v, float* red) {
    int w = threadIdx.x >> 5, l = threadIdx.x & 31;
    v = warp_sum(v);
    if (l == 0) red[w] = v;
    __syncthreads();
    float r = (l < 16) ? red[l] : 0.0f;
    r = warp_sum(r);
    __syncthreads();
    return r;
}
__device__ __forceinline__ float block_max512(float v, float* red) {
    int w = threadIdx.x >> 5, l = threadIdx.x & 31;
    v = warp_max(v);
    if (l == 0) red[w] = v;
    __syncthreads();
    float r = (l < 16) ? red[l] : -1e30f;
    r = warp_max(r);
    __syncthreads();
    return r;
}

// ---------------- generic tiled fp32 GEMM: C = A(MxK) * B(NxK)^T + bias ----
// 128x128 tile, BK=8, 256 threads, 8x8 microtile. K must be a multiple of 8.
__global__ __launch_bounds__(256) void sgemm_nt(
    const float* __restrict__ A, const float* __restrict__ Bm,
    const float* __restrict__ bias, float* __restrict__ C,
    int M, int Nc, int K)
{
    __shared__ float As[8][128];
    __shared__ float Bs[8][128];
    int bm = blockIdx.y * 128, bn = blockIdx.x * 128;
    int tid = threadIdx.x;
    int tx = (tid & 15) * 8;
    int ty = (tid >> 4) * 8;

    float acc[8][8];
#pragma unroll
    for (int i = 0; i < 8; i++)
#pragma unroll
        for (int j = 0; j < 8; j++) acc[i][j] = 0.0f;

    for (int k0 = 0; k0 < K; k0 += 8) {
#pragma unroll
        for (int i = tid; i < 1024; i += 256) {
            int m = i >> 3, k = i & 7;
            int gm = bm + m;
            As[k][m] = (gm < M) ? A[(size_t)gm * K + k0 + k] : 0.0f;
        }
#pragma unroll
        for (int i = tid; i < 1024; i += 256) {
            int n = i >> 3, k = i & 7;
            int gn = bn + n;
            Bs[k][n] = (gn < Nc) ? Bm[(size_t)gn * K + k0 + k] : 0.0f;
        }
        __syncthreads();
#pragma unroll
        for (int k = 0; k < 8; k++) {
            float4 a0 = *reinterpret_cast<const float4*>(&As[k][ty]);
            float4 a1 = *reinterpret_cast<const float4*>(&As[k][ty + 4]);
            float4 b0 = *reinterpret_cast<const float4*>(&Bs[k][tx]);
            float4 b1 = *reinterpret_cast<const float4*>(&Bs[k][tx + 4]);
            float av[8] = {a0.x, a0.y, a0.z, a0.w, a1.x, a1.y, a1.z, a1.w};
            float bv[8] = {b0.x, b0.y, b0.z, b0.w, b1.x, b1.y, b1.z, b1.w};
#pragma unroll
            for (int i = 0; i < 8; i++)
#pragma unroll
                for (int j = 0; j < 8; j++)
                    acc[i][j] = fmaf(av[i], bv[j], acc[i][j]);
        }
        __syncthreads();
    }
#pragma unroll
    for (int i = 0; i < 8; i++) {
        int gm = bm + ty + i;
        if (gm >= M) continue;
#pragma unroll
        for (int j = 0; j < 8; j++) {
            int gn = bn + tx + j;
            if (gn < Nc)
                C[(size_t)gm * Nc + gn] = acc[i][j] + (bias ? bias[gn] : 0.0f);
        }
    }
}

// ---------------- skinny GEMM for M=32 with K-splitting ---------------------
// Computes partials: P[slot][32][NC] with slot = blockIdx.y covering K-chunk of 64.
// P[slot][b][n0+n] = sum_{k in chunk} A[b,k] * B[n0+n,k]
// grid = (NC/64, K/64), 256 threads.
__global__ __launch_bounds__(256) void skinny_gemm64(
    const float* __restrict__ A, int K,
    const float* __restrict__ Bm,
    float* __restrict__ P, int NC)
{
    __shared__ float As[64][36];   // [k][b], padded
    __shared__ float Bs[64][65];   // [k][n], padded
    int k0 = blockIdx.y * 64, n0 = blockIdx.x * 64;
    int tid = threadIdx.x;

#pragma unroll
    for (int i = tid; i < 32 * 64; i += 256) {
        int b = i >> 6, k = i & 63;
        As[k][b] = A[(size_t)b * K + k0 + k];
    }
#pragma unroll
    for (int i = tid; i < 64 * 64; i += 256) {
        int n = i >> 6, k = i & 63;
        Bs[k][n] = Bm[(size_t)(n0 + n) * K + k0 + k];
    }
    __syncthreads();

    int nl = tid & 63, bq = tid >> 6;     // 4 b-groups of 8
    float acc[8] = {0.f, 0.f, 0.f, 0.f, 0.f, 0.f, 0.f, 0.f};
#pragma unroll 8
    for (int k = 0; k < 64; k++) {
        float w = Bs[k][nl];
        const float4* ap = reinterpret_cast<const float4*>(&As[k][bq * 8]);
        float4 a0 = ap[0], a1 = ap[1];
        acc[0] = fmaf(a0.x, w, acc[0]); acc[1] = fmaf(a0.y, w, acc[1]);
        acc[2] = fmaf(a0.z, w, acc[2]); acc[3] = fmaf(a0.w, w, acc[3]);
        acc[4] = fmaf(a1.x, w, acc[4]); acc[5] = fmaf(a1.y, w, acc[5]);
        acc[6] = fmaf(a1.z, w, acc[6]); acc[7] = fmaf(a1.w, w, acc[7]);
    }
    float* dst = P + (size_t)blockIdx.y * 32 * NC + (size_t)(bq * 8) * NC + n0 + nl;
#pragma unroll
    for (int j = 0; j < 8; j++) dst[(size_t)j * NC] = acc[j];
}

// ---------------- attention step: energies + softmax + ctx + z assembly -----
// grid = 32 (one CTA per batch), 512 threads.
__global__ __launch_bounds__(512) void attn_step(
    const float* __restrict__ attn_v,
    const int* __restrict__ tgt,
    const float* __restrict__ emb,
    int t)
{
    int b = blockIdx.x, tid = threadIdx.x;
    __shared__ float hwh[DH];
    __shared__ float vs[DH];
    __shared__ float sc[NN];
    __shared__ float red[16];

    // reduce hWh partials (8 K-slots)
    {
        float s = 0.0f;
#pragma unroll
        for (int s8 = 0; s8 < 8; s8++)
            s += g_phwh[((size_t)s8 * BB + b) * DH + tid];
        hwh[tid] = s;
        vs[tid] = attn_v[tid];
    }
    __syncthreads();

    // scores: e_n = sum_d tanh(hWh[d] + Wk_keys[b,n,d]) * v[d]
    int w = tid >> 5, l = tid & 31;
    for (int n = w; n < NN; n += 16) {
        const float* wk = &g_Wk[((size_t)b * NN + n) * DH];
        float e = 0.0f;
#pragma unroll 4
        for (int k = l; k < DH; k += 32)
            e = fmaf(tanh_fast(hwh[k] + wk[k]), vs[k], e);
        e = warp_sum(e);
        if (l == 0) sc[n] = e;
    }
    __syncthreads();

    // softmax over N=196
    float m = (tid < NN) ? sc[tid] : -1e30f;
    m = block_max512(m, red);
    float ex = 0.0f;
    if (tid < NN) { ex = expf(sc[tid] - m); sc[tid] = ex; }
    float ssum = block_sum512(ex, red);
    float inv = 1.0f / ssum;
    __syncthreads();

    // ctx[d] = (sum_n e_n * keys[b,n,d]) * inv ; d = tid
    float ctx = 0.0f;
    const float* kb = &g_keys[(size_t)b * NN * DH];
    for (int n = 0; n < NN; n++)
        ctx = fmaf(sc[n], kb[(size_t)n * DH + tid], ctx);
    ctx *= inv;

    g_z[b * 2 * DH + DH + tid] = ctx;
    int id = tgt[b * TT + t];
    g_z[b * 2 * DH + tid] = emb[(size_t)id * DH + tid];
}

// ---------------- LSTM cell + layernorm -------------------------------------
// grid = 32, 512 threads (d = tid). Sums gate partials, applies cell + LN.
__global__ __launch_bounds__(512) void cell_step(
    const float* __restrict__ b_ih, const float* __restrict__ b_hh,
    const float* __restrict__ lnw, const float* __restrict__ lnb,
    int t)
{
    int b = blockIdx.x, d = threadIdx.x;
    __shared__ float red[16];

    float gi = 0.f, gf = 0.f, gg = 0.f, go = 0.f;
#pragma unroll
    for (int s = 0; s < 16; s++) {
        const float* p = g_pih + ((size_t)s * BB + b) * 2048;
        gi += p[d]; gf += p[DH + d]; gg += p[2 * DH + d]; go += p[3 * DH + d];
    }
#pragma unroll
    for (int s = 0; s < 8; s++) {
        const float* p = g_phh + ((size_t)s * BB + b) * 2048;
        gi += p[d]; gf += p[DH + d]; gg += p[2 * DH + d]; go += p[3 * DH + d];
    }
    gi += b_ih[d] + b_hh[d];
    gf += b_ih[DH + d] + b_hh[DH + d];
    gg += b_ih[2 * DH + d] + b_hh[2 * DH + d];
    go += b_ih[3 * DH + d] + b_hh[3 * DH + d];

    float c = g_c[b * DH + d];
    float cn = sigmoidf_acc(gf) * c + sigmoidf_acc(gi) * tanhf(gg);
    float hr = sigmoidf_acc(go) * tanhf(cn);
    g_c[b * DH + d] = cn;

    // layernorm over 512
    float mu = block_sum512(hr, red) * (1.0f / DH);
    float va = block_sum512(hr * hr, red) * (1.0f / DH) - mu * mu;
    float hn = (hr - mu) * rsqrtf(va + 1e-5f) * lnw[d] + lnb[d];

    g_h[b * DH + d] = hn;
    g_H[((size_t)b * TT + t) * DH + d] = hn;
}

// ---------------- launcher ---------------------------------------------------
extern "C" void kernel_launch(void* const* d_in, const int* in_sizes, int n_in,
                              void* d_out, int out_size)
{
    (void)in_sizes; (void)n_in; (void)out_size;
    const float* patches = (const float*)d_in[0];
    const float* cls     = (const float*)d_in[1];
    const int*   tgt     = (const int*)  d_in[2];
    const float* emb     = (const float*)d_in[3];
    const float* kv_W    = (const float*)d_in[4];
    const float* kv_b    = (const float*)d_in[5];
    const float* ih_W    = (const float*)d_in[6];
    const float* ih_b    = (const float*)d_in[7];
    const float* ic_W    = (const float*)d_in[8];
    const float* ic_b    = (const float*)d_in[9];
    const float* attn_Wh = (const float*)d_in[10];
    const float* attn_Wk = (const float*)d_in[11];
    const float* attn_v  = (const float*)d_in[12];
    const float* W_ih    = (const float*)d_in[13];
    const float* W_hh    = (const float*)d_in[14];
    const float* b_ih    = (const float*)d_in[15];
    const float* b_hh    = (const float*)d_in[16];
    const float* ln_w    = (const float*)d_in[17];
    const float* ln_b    = (const float*)d_in[18];
    const float* out_W   = (const float*)d_in[19];
    const float* out_b   = (const float*)d_in[20];
    float* out = (float*)d_out;

    float *p_keys, *p_Wk, *p_h, *p_c, *p_z, *p_H, *p_pih, *p_phh, *p_phwh;
    cudaGetSymbolAddress((void**)&p_keys, g_keys);
    cudaGetSymbolAddress((void**)&p_Wk,   g_Wk);
    cudaGetSymbolAddress((void**)&p_h,    g_h);
    cudaGetSymbolAddress((void**)&p_c,    g_c);
    cudaGetSymbolAddress((void**)&p_z,    g_z);
    cudaGetSymbolAddress((void**)&p_H,    g_H);
    cudaGetSymbolAddress((void**)&p_pih,  g_pih);
    cudaGetSymbolAddress((void**)&p_phh,  g_phh);
    cudaGetSymbolAddress((void**)&p_phwh, g_phwh);

    // ---- precompute ----
    // keys = patches @ kv_W^T + kv_b : [6272, 512], K=768
    sgemm_nt<<<dim3(DH / 128, (BB * NN) / 128), 256>>>(patches, kv_W, kv_b, p_keys, BB * NN, DH, DIMG);
    // Wk_keys = keys @ attn_Wk^T : [6272, 512], K=512
    sgemm_nt<<<dim3(DH / 128, (BB * NN) / 128), 256>>>(p_keys, attn_Wk, nullptr, p_Wk, BB * NN, DH, DH);
    // h0 / c0
    sgemm_nt<<<dim3(DH / 128, 1), 256>>>(cls, ih_W, ih_b, p_h, BB, DH, DIMG);
    sgemm_nt<<<dim3(DH / 128, 1), 256>>>(cls, ic_W, ic_b, p_c, BB, DH, DIMG);

    // ---- recurrence ----
    for (int t = 0; t < TT; t++) {
        // hWh = h @ attn_Wh^T (partials, 8 K-slots)
        skinny_gemm64<<<dim3(DH / 64, DH / 64), 256>>>(p_h, DH, attn_Wh, p_phwh, DH);
        // attention: scores -> softmax -> ctx; assemble z = [x_t | ctx]
        attn_step<<<BB, 512>>>(attn_v, tgt, emb, t);
        // gates partials: z @ W_ih^T (K=1024 -> 16 slots), h @ W_hh^T (K=512 -> 8 slots)
        skinny_gemm64<<<dim3(2048 / 64, 1024 / 64), 256>>>(p_z, 2 * DH, W_ih, p_pih, 2048);
        skinny_gemm64<<<dim3(2048 / 64, 512 / 64), 256>>>(p_h, DH, W_hh, p_phh, 2048);
        // cell + layernorm; stores h_new into g_h and g_H[:, t, :]
        cell_step<<<BB, 512>>>(b_ih, b_hh, ln_w, ln_b, t);
    }

    // ---- deferred logits: out[b,t,:] = H[b*T+t,:] @ out_W^T + out_b ----
    sgemm_nt<<<dim3((VV + 127) / 128, (BB * TT) / 128), 256>>>(p_H, out_W, out_b, out, BB * TT, VV, DH);
}